// round 2
// baseline (speedup 1.0000x reference)
#include <cuda_runtime.h>
#include <math.h>

#define HD   512      // hidden
#define ID   768      // input
#define BB   32       // batch
#define TT   512      // time
#define G4   2048     // 4*HD

// ---------------- scratch (static device memory; no allocs) ----------------
__device__ float    g_gx[(size_t)TT * BB * G4];   // [t][b][col]  (128 MiB)
__device__ float    g_hbuf[2][BB * HD];           // double-buffered h, [b][k]
__device__ unsigned g_bar_count;
__device__ unsigned g_bar_gen;

// ---------------- init: reset barrier, seed h with h0[dir=0] ----------------
__global__ void init_kernel(const float* __restrict__ h0)
{
    int idx = blockIdx.x * blockDim.x + threadIdx.x;
    if (idx == 0) { g_bar_count = 0; g_bar_gen = 0; }
    if (idx < BB * HD) g_hbuf[0][idx] = h0[idx];
}

// ---------------- gx GEMM: gx[t*32+b][n] = x[b][t][:] . w_ih[n][:] + bias[n] ----------------
#define BM 128
#define BN 64
#define BK 16

__global__ __launch_bounds__(256) void gx_gemm_kernel(
    const float* __restrict__ x,     // [B][T][I]
    const float* __restrict__ w,     // [2048][768]
    const float* __restrict__ b1,
    const float* __restrict__ b2)
{
    __shared__ float As[BK][BM + 4];
    __shared__ float Bs[BK][BN + 4];

    int tid  = threadIdx.x;
    int brow = blockIdx.x;   // 0..127   (M tiles)
    int bcol = blockIdx.y;   // 0..31    (N tiles)
    int ty = tid >> 4;       // 0..15
    int tx = tid & 15;       // 0..15

    float acc[8][4];
    #pragma unroll
    for (int i = 0; i < 8; i++)
        #pragma unroll
        for (int j = 0; j < 4; j++) acc[i][j] = 0.f;

    for (int k0 = 0; k0 < ID; k0 += BK) {
        #pragma unroll
        for (int i = 0; i < 8; i++) {           // A tile: 128x16
            int e  = i * 256 + tid;
            int r  = e >> 4;
            int kk = e & 15;
            int m  = brow * BM + r;
            int b  = m & 31, t = m >> 5;
            As[kk][r] = x[((size_t)b * TT + t) * ID + k0 + kk];
        }
        #pragma unroll
        for (int i = 0; i < 4; i++) {           // B tile: 64x16
            int e  = i * 256 + tid;
            int n  = e >> 4;
            int kk = e & 15;
            Bs[kk][n] = w[(size_t)(bcol * BN + n) * ID + k0 + kk];
        }
        __syncthreads();

        #pragma unroll
        for (int kk = 0; kk < BK; kk++) {
            const float4* ap = (const float4*)&As[kk][ty * 8];
            float4 a0 = ap[0], a1 = ap[1];
            float4 bv = *(const float4*)&Bs[kk][tx * 4];
            float a[8] = {a0.x, a0.y, a0.z, a0.w, a1.x, a1.y, a1.z, a1.w};
            float bb4[4] = {bv.x, bv.y, bv.z, bv.w};
            #pragma unroll
            for (int i = 0; i < 8; i++)
                #pragma unroll
                for (int j = 0; j < 4; j++) acc[i][j] += a[i] * bb4[j];
        }
        __syncthreads();
    }

    int ncol = bcol * BN + tx * 4;
    float bias[4];
    #pragma unroll
    for (int j = 0; j < 4; j++) bias[j] = b1[ncol + j] + b2[ncol + j];

    #pragma unroll
    for (int i = 0; i < 8; i++) {
        int m = brow * BM + ty * 8 + i;
        float4 v;
        v.x = acc[i][0] + bias[0];
        v.y = acc[i][1] + bias[1];
        v.z = acc[i][2] + bias[2];
        v.w = acc[i][3] + bias[3];
        *(float4*)&g_gx[(size_t)m * G4 + ncol] = v;
    }
}

// ---------------- backward direction: exactly ONE cell step on x[:,T-1,:] ----------------
__global__ __launch_bounds__(256) void lstm_bwd_step_kernel(
    const float* __restrict__ x,
    const float* __restrict__ h0,    // [2][B][H]
    const float* __restrict__ c0,
    const float* __restrict__ w_ih,  // [2048][768]
    const float* __restrict__ w_hh,  // [2048][512]
    const float* __restrict__ b_ih,
    const float* __restrict__ b_hh,
    float* __restrict__ out)
{
    int tid = threadIdx.x;
    int b = tid & 31;
    int j = blockIdx.x * 8 + (tid >> 5);   // 64 blocks x 8 -> 512

    float acc[4] = {0.f, 0.f, 0.f, 0.f};
    const float* xrow = x + ((size_t)b * TT + (TT - 1)) * ID;
    #pragma unroll 4
    for (int k = 0; k < ID; k++) {
        float xv = xrow[k];
        #pragma unroll
        for (int g = 0; g < 4; g++)
            acc[g] += xv * w_ih[(size_t)(g * HD + j) * ID + k];
    }
    const float* hrow = h0 + BB * HD + (size_t)b * HD;   // dir 1
    #pragma unroll 4
    for (int k = 0; k < HD; k++) {
        float hv = hrow[k];
        #pragma unroll
        for (int g = 0; g < 4; g++)
            acc[g] += hv * w_hh[(size_t)(g * HD + j) * HD + k];
    }
    #pragma unroll
    for (int g = 0; g < 4; g++) acc[g] += b_ih[g * HD + j] + b_hh[g * HD + j];

    float ig = 1.f / (1.f + __expf(-acc[0]));
    float fg = 1.f / (1.f + __expf(-acc[1]));
    float gg = tanhf(acc[2]);
    float og = 1.f / (1.f + __expf(-acc[3]));
    float c  = fg * c0[BB * HD + (size_t)b * HD + j] + ig * gg;
    float h  = og * tanhf(c);
    out[b * 1024 + 512 + j] = fmaxf(h, 0.f);
}

// ---------------- forward recurrence: persistent kernel, 1 grid barrier/step ----------------
// CTA bx owns hidden units j in [4*bx, 4*bx+4), all 4 gates for them (16 w_hh rows).
// SMEM: w slice 16x512 (32KB, resident all steps), staged h 32x516 (padded), partials, gx stage.
#define SMEM_FLOATS (16*512 + 32*516 + 2*16*32 + 4*32*4)
#define SMEM_BYTES  (SMEM_FLOATS * 4)

__global__ __launch_bounds__(256) void lstm_fwd_kernel(
    const float* __restrict__ c0,
    const float* __restrict__ w_hh,   // [2048][512]
    float* __restrict__ out)
{
    extern __shared__ float sm[];
    float* w_s  = sm;                        // [16][512]   r = g*4+u
    float* h_s  = sm + 16 * 512;             // [32][516]   (pad 4 -> conflict-free LDS.128)
    float* part = h_s + 32 * 516;            // [2][16][32] k-split partials
    float* gxs  = part + 2 * 16 * 32;        // [4][32][4]  [g][b][u]

    int tid  = threadIdx.x;
    int bx   = blockIdx.x;       // 0..127
    int lane = tid & 31;
    int warp = tid >> 5;

    // load w_hh slice: local row r -> global row  (r>>2)*512 + bx*4 + (r&3)
    for (int i = tid; i < 16 * 128; i += 256) {
        int r  = i >> 7;
        int kq = i & 127;
        int col = (r >> 2) * HD + bx * 4 + (r & 3);
        *(float4*)&w_s[r * HD + kq * 4] =
            *(const float4*)&w_hh[(size_t)col * HD + kq * 4];
    }

    int u = tid >> 5;            // valid for tid<128
    int b = lane;
    int j = bx * 4 + u;
    float c = 0.f, hv = 0.f;
    if (tid < 128) c = c0[(size_t)b * HD + j];

    unsigned gen = 0;
    for (int step = 0; step < TT; step++) {
        int p = step & 1;
        const float* hsrc = g_hbuf[p];

        // stage h (64KB) from L2 (bypass L1: cross-CTA producer/consumer)
        for (int i = tid; i < 4096; i += 256) {
            int bb = i >> 7;
            int kq = i & 127;
            float4 v = __ldcg((const float4*)(hsrc + bb * HD + kq * 4));
            *(float4*)&h_s[bb * 516 + kq * 4] = v;
        }
        // stage this step's gx slice: [g][b] float4 over u
        if (tid < 128) {
            int g = tid >> 5;
            float4 gv = __ldcg((const float4*)&g_gx[((size_t)(step * BB + b)) * G4 + g * HD + bx * 4]);
            *(float4*)&gxs[(g * 32 + b) * 4] = gv;
        }
        __syncthreads();

        // gate dots: warp -> (k-half, 4 rows), lane -> batch
        {
            int half = warp >> 2;
            int rq   = (warp & 3) * 4;
            const float* hp = h_s + lane * 516 + half * 256;
            const float* w0 = w_s + (rq + 0) * HD + half * 256;
            const float* w1 = w_s + (rq + 1) * HD + half * 256;
            const float* w2 = w_s + (rq + 2) * HD + half * 256;
            const float* w3 = w_s + (rq + 3) * HD + half * 256;
            float a0 = 0.f, a1 = 0.f, a2 = 0.f, a3 = 0.f;
            #pragma unroll 16
            for (int k = 0; k < 256; k += 4) {
                float4 h4 = *(const float4*)(hp + k);
                float4 v0 = *(const float4*)(w0 + k);
                a0 += h4.x * v0.x; a0 += h4.y * v0.y; a0 += h4.z * v0.z; a0 += h4.w * v0.w;
                float4 v1 = *(const float4*)(w1 + k);
                a1 += h4.x * v1.x; a1 += h4.y * v1.y; a1 += h4.z * v1.z; a1 += h4.w * v1.w;
                float4 v2 = *(const float4*)(w2 + k);
                a2 += h4.x * v2.x; a2 += h4.y * v2.y; a2 += h4.z * v2.z; a2 += h4.w * v2.w;
                float4 v3 = *(const float4*)(w3 + k);
                a3 += h4.x * v3.x; a3 += h4.y * v3.y; a3 += h4.z * v3.z; a3 += h4.w * v3.w;
            }
            part[(half * 16 + rq + 0) * 32 + lane] = a0;
            part[(half * 16 + rq + 1) * 32 + lane] = a1;
            part[(half * 16 + rq + 2) * 32 + lane] = a2;
            part[(half * 16 + rq + 3) * 32 + lane] = a3;
        }
        __syncthreads();

        // CTA-local elementwise cell update (thread t<128 owns (u,b), c in register)
        if (tid < 128) {
            float gate[4];
            #pragma unroll
            for (int g = 0; g < 4; g++) {
                int r = g * 4 + u;
                gate[g] = part[r * 32 + b] + part[512 + r * 32 + b]
                        + gxs[(g * 32 + b) * 4 + u];
            }
            float ig = 1.f / (1.f + __expf(-gate[0]));
            float fg = 1.f / (1.f + __expf(-gate[1]));
            float gg = tanhf(gate[2]);
            float og = 1.f / (1.f + __expf(-gate[3]));
            c  = fg * c + ig * gg;
            hv = og * tanhf(c);
            g_hbuf[1 - p][(size_t)b * HD + j] = hv;
        }

        // ---- grid barrier (all 128 CTAs co-resident: 105KB smem -> 1 CTA/SM) ----
        gen++;
        __syncthreads();
        if (tid == 0) {
            __threadfence();
            unsigned prev = atomicAdd(&g_bar_count, 1);
            if (prev == gridDim.x - 1) {
                atomicExch(&g_bar_count, 0);
                __threadfence();
                atomicExch(&g_bar_gen, gen);
            } else {
                while (*((volatile unsigned*)&g_bar_gen) < gen) { }
                __threadfence();
            }
        }
        __syncthreads();
    }

    if (tid < 128) out[b * 1024 + j] = fmaxf(hv, 0.f);
}

// ---------------- launch ----------------
extern "C" void kernel_launch(void* const* d_in, const int* in_sizes, int n_in,
                              void* d_out, int out_size)
{
    const float* x      = (const float*)d_in[0];
    const float* h0     = (const float*)d_in[1];
    const float* c0     = (const float*)d_in[2];
    const float* w_ih_f = (const float*)d_in[3];
    const float* w_hh_f = (const float*)d_in[4];
    const float* b_ih_f = (const float*)d_in[5];
    const float* b_hh_f = (const float*)d_in[6];
    const float* w_ih_b = (const float*)d_in[7];
    const float* w_hh_b = (const float*)d_in[8];
    const float* b_ih_b = (const float*)d_in[9];
    const float* b_hh_b = (const float*)d_in[10];
    float* out = (float*)d_out;

    // idempotent; needed for >48KB dynamic smem
    cudaFuncSetAttribute(lstm_fwd_kernel,
                         cudaFuncAttributeMaxDynamicSharedMemorySize, SMEM_BYTES);

    init_kernel<<<64, 256>>>(h0);

    dim3 gg(128, 32);
    gx_gemm_kernel<<<gg, 256>>>(x, w_ih_f, b_ih_f, b_hh_f);

    lstm_bwd_step_kernel<<<64, 256>>>(x, h0, c0, w_ih_b, w_hh_b, b_ih_b, b_hh_b, out);

    lstm_fwd_kernel<<<128, 256, SMEM_BYTES>>>(c0, w_hh_f, out);
}

// round 3
// speedup vs baseline: 1.1311x; 1.1311x over previous
#include <cuda_runtime.h>
#include <math.h>

#define HD   512      // hidden
#define ID   768      // input
#define BB   32       // batch
#define TT   512      // time
#define G4   2048     // 4*HD

// ---------------- f32x2 packed helpers (Blackwell FFMA2) ----------------
__device__ __forceinline__ void ffma2(unsigned long long& d,
                                      unsigned long long a,
                                      unsigned long long b) {
    asm("fma.rn.f32x2 %0, %1, %2, %0;" : "+l"(d) : "l"(a), "l"(b));
}
__device__ __forceinline__ unsigned long long pack2(float lo, float hi) {
    unsigned long long r;
    asm("mov.b64 %0, {%1, %2};" : "=l"(r) : "f"(lo), "f"(hi));
    return r;
}
__device__ __forceinline__ void unpack2(unsigned long long v, float& lo, float& hi) {
    asm("mov.b64 {%0, %1}, %2;" : "=f"(lo), "=f"(hi) : "l"(v));
}

// ---------------- scratch (static device memory; no allocs) ----------------
__device__ float    g_gx[(size_t)TT * BB * G4];   // [t][b][col]  (128 MiB)
__device__ float    g_hbuf[2][BB * HD];           // double-buffered h, [b][k]
__device__ unsigned g_bar_count;
__device__ unsigned g_bar_gen;

// ---------------- init: reset barrier, seed h with h0[dir=0] ----------------
__global__ void init_kernel(const float* __restrict__ h0)
{
    int idx = blockIdx.x * blockDim.x + threadIdx.x;
    if (idx == 0) { g_bar_count = 0; g_bar_gen = 0; }
    if (idx < BB * HD) g_hbuf[0][idx] = h0[idx];
}

// ---------------- gx GEMM: gx[t*32+b][n] = x[b][t][:] . w_ih[n][:] + bias[n] ----------------
#define BM 128
#define BN 64
#define BK 16

__global__ __launch_bounds__(256) void gx_gemm_kernel(
    const float* __restrict__ x,     // [B][T][I]
    const float* __restrict__ w,     // [2048][768]
    const float* __restrict__ b1,
    const float* __restrict__ b2)
{
    __shared__ float As[BK][BM + 4];
    __shared__ float Bs[BK][BN + 4];

    int tid  = threadIdx.x;
    int brow = blockIdx.x;   // 0..127   (M tiles)
    int bcol = blockIdx.y;   // 0..31    (N tiles)
    int ty = tid >> 4;       // 0..15
    int tx = tid & 15;       // 0..15

    // acc2[ip][j] = f32x2 accumulator for rows (ty*8+2ip, ty*8+2ip+1), col tx*4+j
    unsigned long long acc2[4][4];
    #pragma unroll
    for (int i = 0; i < 4; i++)
        #pragma unroll
        for (int j = 0; j < 4; j++) acc2[i][j] = 0ull;

    for (int k0 = 0; k0 < ID; k0 += BK) {
        #pragma unroll
        for (int i = 0; i < 8; i++) {           // A tile: 128x16
            int e  = i * 256 + tid;
            int r  = e >> 4;
            int kk = e & 15;
            int m  = brow * BM + r;
            int b  = m & 31, t = m >> 5;
            As[kk][r] = x[((size_t)b * TT + t) * ID + k0 + kk];
        }
        #pragma unroll
        for (int i = 0; i < 4; i++) {           // B tile: 64x16
            int e  = i * 256 + tid;
            int n  = e >> 4;
            int kk = e & 15;
            Bs[kk][n] = w[(size_t)(bcol * BN + n) * ID + k0 + kk];
        }
        __syncthreads();

        #pragma unroll
        for (int kk = 0; kk < BK; kk++) {
            // a pairs: natural (contiguous over m)
            ulonglong2 av0 = *(const ulonglong2*)&As[kk][ty * 8];
            ulonglong2 av1 = *(const ulonglong2*)&As[kk][ty * 8 + 4];
            unsigned long long ap[4] = {av0.x, av0.y, av1.x, av1.y};
            // b splats
            float4 bv = *(const float4*)&Bs[kk][tx * 4];
            unsigned long long bsp[4];
            bsp[0] = pack2(bv.x, bv.x);
            bsp[1] = pack2(bv.y, bv.y);
            bsp[2] = pack2(bv.z, bv.z);
            bsp[3] = pack2(bv.w, bv.w);
            #pragma unroll
            for (int ip = 0; ip < 4; ip++)
                #pragma unroll
                for (int j = 0; j < 4; j++)
                    ffma2(acc2[ip][j], ap[ip], bsp[j]);
        }
        __syncthreads();
    }

    int ncol = bcol * BN + tx * 4;
    float bias[4];
    #pragma unroll
    for (int j = 0; j < 4; j++) bias[j] = b1[ncol + j] + b2[ncol + j];

    #pragma unroll
    for (int ip = 0; ip < 4; ip++) {
        float lo[4], hi[4];
        #pragma unroll
        for (int j = 0; j < 4; j++) unpack2(acc2[ip][j], lo[j], hi[j]);
        int m0 = brow * BM + ty * 8 + 2 * ip;
        float4 v0 = {lo[0] + bias[0], lo[1] + bias[1], lo[2] + bias[2], lo[3] + bias[3]};
        float4 v1 = {hi[0] + bias[0], hi[1] + bias[1], hi[2] + bias[2], hi[3] + bias[3]};
        *(float4*)&g_gx[(size_t)m0 * G4 + ncol] = v0;
        *(float4*)&g_gx[(size_t)(m0 + 1) * G4 + ncol] = v1;
    }
}

// ---------------- backward direction: exactly ONE cell step on x[:,T-1,:] ----------------
__global__ __launch_bounds__(256) void lstm_bwd_step_kernel(
    const float* __restrict__ x,
    const float* __restrict__ h0,    // [2][B][H]
    const float* __restrict__ c0,
    const float* __restrict__ w_ih,  // [2048][768]
    const float* __restrict__ w_hh,  // [2048][512]
    const float* __restrict__ b_ih,
    const float* __restrict__ b_hh,
    float* __restrict__ out)
{
    int tid = threadIdx.x;
    int b = tid & 31;
    int j = blockIdx.x * 8 + (tid >> 5);   // 64 blocks x 8 -> 512

    float acc[4] = {0.f, 0.f, 0.f, 0.f};
    const float* xrow = x + ((size_t)b * TT + (TT - 1)) * ID;
    #pragma unroll 4
    for (int k = 0; k < ID; k++) {
        float xv = xrow[k];
        #pragma unroll
        for (int g = 0; g < 4; g++)
            acc[g] += xv * w_ih[(size_t)(g * HD + j) * ID + k];
    }
    const float* hrow = h0 + BB * HD + (size_t)b * HD;   // dir 1
    #pragma unroll 4
    for (int k = 0; k < HD; k++) {
        float hv = hrow[k];
        #pragma unroll
        for (int g = 0; g < 4; g++)
            acc[g] += hv * w_hh[(size_t)(g * HD + j) * HD + k];
    }
    #pragma unroll
    for (int g = 0; g < 4; g++) acc[g] += b_ih[g * HD + j] + b_hh[g * HD + j];

    float ig = 1.f / (1.f + __expf(-acc[0]));
    float fg = 1.f / (1.f + __expf(-acc[1]));
    float gg = tanhf(acc[2]);
    float og = 1.f / (1.f + __expf(-acc[3]));
    float c  = fg * c0[BB * HD + (size_t)b * HD + j] + ig * gg;
    float h  = og * tanhf(c);
    out[b * 1024 + 512 + j] = fmaxf(h, 0.f);
}

// ---------------- forward recurrence: persistent kernel, 1 grid barrier/step ----------------
// 512 threads, 16 warps. warp = (k-eighth e = warp>>1, row-half rg = warp&1).
// Warp computes rows [rg*8, rg*8+8) over k in [e*64, e*64+64) for all 32 batches (lane=batch).
// FFMA2 paired over k (both operand pairs contiguous: no splats).
#define SMEM_FLOATS (16*512 + 32*516 + 8*16*32 + 4*32*4)
#define SMEM_BYTES  (SMEM_FLOATS * 4)

__global__ __launch_bounds__(512) void lstm_fwd_kernel(
    const float* __restrict__ c0,
    const float* __restrict__ w_hh,   // [2048][512]
    float* __restrict__ out)
{
    extern __shared__ float sm[];
    float* w_s  = sm;                        // [16][512]   r = g*4+u
    float* h_s  = sm + 16 * 512;             // [32][516]   pad 4 -> conflict-free LDS.128
    float* part = h_s + 32 * 516;            // [8][16][32] k-eighth partials
    float* gxs  = part + 8 * 16 * 32;        // [4][32][4]  [g][b][u]

    int tid  = threadIdx.x;
    int bx   = blockIdx.x;       // 0..127
    int lane = tid & 31;
    int warp = tid >> 5;         // 0..15
    int e    = warp >> 1;        // k-eighth 0..7
    int rg   = warp & 1;         // row half 0/1 -> rows rg*8..rg*8+7

    // load w_hh slice: local row r -> global row (r>>2)*512 + bx*4 + (r&3)
    for (int i = tid; i < 16 * 128; i += 512) {
        int r  = i >> 7;
        int kq = i & 127;
        int col = (r >> 2) * HD + bx * 4 + (r & 3);
        *(float4*)&w_s[r * HD + kq * 4] =
            *(const float4*)&w_hh[(size_t)col * HD + kq * 4];
    }

    int u = tid >> 5;            // valid for tid<128 (0..3)
    int b = lane;
    int j = bx * 4 + u;
    float c = 0.f, hv = 0.f;
    if (tid < 128) c = c0[(size_t)b * HD + j];

    const float* hp0 = h_s + lane * 516 + e * 64;
    const float* wb0 = w_s + (rg * 8) * HD + e * 64;

    unsigned gen = 0;
    for (int step = 0; step < TT; step++) {
        int p = step & 1;
        const float* hsrc = g_hbuf[p];

        // stage h (64KB) from L2 (bypass L1: cross-CTA producer/consumer)
        for (int i = tid; i < 4096; i += 512) {
            int bb = i >> 7;
            int kq = i & 127;
            float4 v = __ldcg((const float4*)(hsrc + bb * HD + kq * 4));
            *(float4*)&h_s[bb * 516 + kq * 4] = v;
        }
        // stage this step's gx slice: [g][b] float4 over u
        if (tid < 128) {
            int g = tid >> 5;
            float4 gv = __ldcg((const float4*)&g_gx[((size_t)(step * BB + b)) * G4 + g * HD + bx * 4]);
            *(float4*)&gxs[(g * 32 + b) * 4] = gv;
        }
        __syncthreads();

        // gate dots: 8 rows x 64 k per warp, FFMA2 over k-pairs
        {
            unsigned long long acc[8];
            #pragma unroll
            for (int r = 0; r < 8; r++) acc[r] = 0ull;

            #pragma unroll
            for (int it = 0; it < 16; it++) {
                int k = it * 4;
                ulonglong2 h2 = *(const ulonglong2*)(hp0 + k);   // {h[k],h[k+1]},{h[k+2],h[k+3]}
                #pragma unroll
                for (int r = 0; r < 8; r++) {
                    ulonglong2 w2 = *(const ulonglong2*)(wb0 + r * HD + k);
                    ffma2(acc[r], w2.x, h2.x);
                    ffma2(acc[r], w2.y, h2.y);
                }
            }
            #pragma unroll
            for (int r = 0; r < 8; r++) {
                float lo, hi;
                unpack2(acc[r], lo, hi);
                part[(e * 16 + rg * 8 + r) * 32 + lane] = lo + hi;
            }
        }
        __syncthreads();

        // CTA-local elementwise cell update (thread t<128 owns (u,b), c in register)
        if (tid < 128) {
            float gate[4];
            #pragma unroll
            for (int g = 0; g < 4; g++) {
                int r = g * 4 + u;
                float s = gxs[(g * 32 + b) * 4 + u];
                #pragma unroll
                for (int ee = 0; ee < 8; ee++)
                    s += part[(ee * 16 + r) * 32 + b];
                gate[g] = s;
            }
            float ig = 1.f / (1.f + __expf(-gate[0]));
            float fg = 1.f / (1.f + __expf(-gate[1]));
            float gg = tanhf(gate[2]);
            float og = 1.f / (1.f + __expf(-gate[3]));
            c  = fg * c + ig * gg;
            hv = og * tanhf(c);
            g_hbuf[1 - p][(size_t)b * HD + j] = hv;
        }

        // ---- grid barrier (all 128 CTAs co-resident: 1 CTA/SM) ----
        gen++;
        __syncthreads();
        if (tid == 0) {
            __threadfence();
            unsigned prev = atomicAdd(&g_bar_count, 1);
            if (prev == gridDim.x - 1) {
                atomicExch(&g_bar_count, 0);
                __threadfence();
                atomicExch(&g_bar_gen, gen);
            } else {
                while (*((volatile unsigned*)&g_bar_gen) < gen) { }
                __threadfence();
            }
        }
        __syncthreads();
    }

    if (tid < 128) out[b * 1024 + j] = fmaxf(hv, 0.f);
}

// ---------------- launch ----------------
extern "C" void kernel_launch(void* const* d_in, const int* in_sizes, int n_in,
                              void* d_out, int out_size)
{
    const float* x      = (const float*)d_in[0];
    const float* h0     = (const float*)d_in[1];
    const float* c0     = (const float*)d_in[2];
    const float* w_ih_f = (const float*)d_in[3];
    const float* w_hh_f = (const float*)d_in[4];
    const float* b_ih_f = (const float*)d_in[5];
    const float* b_hh_f = (const float*)d_in[6];
    const float* w_ih_b = (const float*)d_in[7];
    const float* w_hh_b = (const float*)d_in[8];
    const float* b_ih_b = (const float*)d_in[9];
    const float* b_hh_b = (const float*)d_in[10];
    float* out = (float*)d_out;

    cudaFuncSetAttribute(lstm_fwd_kernel,
                         cudaFuncAttributeMaxDynamicSharedMemorySize, SMEM_BYTES);

    init_kernel<<<64, 256>>>(h0);

    dim3 gg(128, 32);
    gx_gemm_kernel<<<gg, 256>>>(x, w_ih_f, b_ih_f, b_hh_f);

    lstm_bwd_step_kernel<<<64, 256>>>(x, h0, c0, w_ih_b, w_hh_b, b_ih_b, b_hh_b, out);

    lstm_fwd_kernel<<<128, 512, SMEM_BYTES>>>(c0, w_hh_f, out);
}